// round 8
// baseline (speedup 1.0000x reference)
#include <cuda_runtime.h>

#define NN 32
#define CC 256
#define SS 30
#define HWD 256        // 16*16 pixels per frame
#define PP 16          // parts
#define PIT 260        // row pitch: 16B-aligned, 2-way worst-case LDS
#define WCH 8          // channels per warp
#define STC 2          // channels per subtile
#define NST 4          // subtiles per warp

__device__ int g_lab64;

// Detect label dtype layout: int64 little-endian -> odd 32-bit words all 0.
__global__ void detect_label_dtype(const int* __restrict__ lab)
{
    if (threadIdx.x == 0) {
        int any = 0;
        #pragma unroll 8
        for (int i = 1; i < 256; i += 2) any |= lab[i];
        g_lab64 = (any == 0) ? 1 : 0;
    }
}

#define CP_ASYNC16(dst, src) \
    asm volatile("cp.async.cg.shared.global [%0], [%1], 16;" :: "r"(dst), "l"(src) : "memory")
#define CP_COMMIT() asm volatile("cp.async.commit_group;" ::: "memory")
#define CP_WAIT(n)  asm volatile("cp.async.wait_group %0;" :: "n"(n) : "memory")

__global__ __launch_bounds__(256, 3)
void part_pool_kernel(const float* __restrict__ x,
                      const void* __restrict__ labels_raw,
                      float* __restrict__ out)
{
    extern __shared__ float tiles[];          // 8 warps * WCH * PIT = 66,560 B
    __shared__ unsigned int pk4w[(HWD + PP * 4) / 4];  // byte pixel lists, 4-padded
    __shared__ float rinv[PP];
    __shared__ int cnt[PP], off4[PP], fill[PP];

    unsigned char* pk4 = (unsigned char*)pk4w;

    const int bid = blockIdx.x;               // 0..3839
    const int f   = bid >> 2;                 // frame
    const int q   = bid & 3;                  // channel quarter (64 channels)
    const int n = f / SS;
    const int s = f % SS;
    const int t = threadIdx.x;
    const int w = t >> 5;
    const int l = t & 31;

    // ---- prologue: per-frame label bucketing -> 4-padded byte pixel lists ----
    if (t < PP) { cnt[t] = 0; fill[t] = 0; }
    __syncthreads();

    int myl;
    if (g_lab64) myl = (int)((const long long*)labels_raw)[(size_t)f * HWD + t];
    else         myl = ((const int*)labels_raw)[(size_t)f * HWD + t];
    myl &= (PP - 1);
    atomicAdd(&cnt[myl], 1);
    __syncthreads();

    if (t == 0) {
        int acc = 0;
        #pragma unroll
        for (int p = 0; p < PP; p++) { off4[p] = acc; acc += (cnt[p] + 3) & ~3; }
    }
    if (t < PP) rinv[t] = (cnt[t] > 0) ? (1.0f / (float)cnt[t]) : 0.0f;
    __syncthreads();
    pk4[off4[myl] + atomicAdd(&fill[myl], 1)] = (unsigned char)t;
    __syncthreads();
    if (t < PP && cnt[t] > 0) {               // pad lists with first pixel
        int o = off4[t];
        unsigned char p0 = pk4[o];
        for (int k = cnt[t]; k & 3; k++) pk4[o + k] = p0;
    }
    __syncthreads();                          // last block-wide barrier

    // ---- warp-autonomous main phase (no __syncthreads below) ----
    // warp w owns channels [q*64 + w*8, +8), split into 4 subtiles of 2.
    float* wbase = tiles + w * (WCH * PIT);
    const unsigned swb = (unsigned)__cvta_generic_to_shared(wbase);
    const int cbase = q * 64 + w * WCH;       // first channel of this warp

    // load roles: lanes 0-15 -> subtile channel 0, lanes 16-31 -> channel 1
    const int cload = l >> 4;
    const int gl    = l & 15;

    // issue ALL subtile loads upfront (4 commit groups, 8 KB in flight/warp)
    #pragma unroll
    for (int st = 0; st < NST; st++) {
        const float* row = x + ((size_t)(n * CC + cbase + st * STC + cload) * SS + s) * HWD;
        unsigned dst = swb + (unsigned)((st * STC + cload) * (PIT * 4));
        #pragma unroll
        for (int k = 0; k < 4; k++) {
            int g = gl + 16 * k;
            CP_ASYNC16(dst + g * 16, row + g * 4);
        }
        CP_COMMIT();
    }

    // compute roles: lane = (part l>>1, channel l&1); lane pairs share a list
    const int p   = l >> 1;
    const int ccl = l & 1;
    const int cN  = cnt[p];
    const int o4  = off4[p];
    const int kN  = (cN + 3) >> 2;
    const float rc = rinv[p];
    const unsigned int* mylist = pk4w + (o4 >> 2);

    #pragma unroll
    for (int st = 0; st < NST; st++) {
        if      (st == 0) CP_WAIT(3);
        else if (st == 1) CP_WAIT(2);
        else if (st == 2) CP_WAIT(1);
        else              CP_WAIT(0);
        __syncwarp();                         // publish lanes' copies warp-wide

        const float* tb = wbase + (st * STC + ccl) * PIT;

        float sum = 0.0f;
        float mx  = -3.0e38f;
        #pragma unroll 2
        for (int k = 0; k < kN; k++) {
            unsigned u = mylist[k];           // broadcast LDS: 4 pixel ids
            float a = tb[u & 255u];
            float b = tb[(u >> 8) & 255u];
            float c = tb[(u >> 16) & 255u];
            float d = tb[u >> 24];
            sum += (a + b) + (c + d);
            mx = fmaxf(fmaxf(mx, fmaxf(a, b)), fmaxf(c, d));
        }

        float r = 0.0f;
        if (cN > 0) {
            int pad = (kN << 2) - cN;         // 0..3 first-pixel duplicates
            if (pad) sum -= (float)pad * tb[pk4[o4]];
            r = sum * rc + fmaxf(mx, -100.0f);   // mean + amax(incl -100 init)
        }

        // store: even lanes = parts 0..15 of channel st*2+0 -> contiguous 64B
        int c = cbase + st * STC + ccl;
        out[((size_t)(n * CC + c) * SS + s) * PP + p] = r;
    }
}

extern "C" void kernel_launch(void* const* d_in, const int* in_sizes, int n_in,
                              void* d_out, int out_size)
{
    const float* x      = (const float*)d_in[0];
    const void*  labels = d_in[1];
    float*       out    = (float*)d_out;

    cudaFuncSetAttribute(part_pool_kernel,
                         cudaFuncAttributeMaxDynamicSharedMemorySize,
                         8 * WCH * PIT * 4);

    detect_label_dtype<<<1, 32>>>((const int*)labels);
    part_pool_kernel<<<NN * SS * 4, 256, 8 * WCH * PIT * 4>>>(x, labels, out);
}

// round 9
// speedup vs baseline: 1.2567x; 1.2567x over previous
#include <cuda_runtime.h>

#define NN 32
#define CC 256
#define SS 30
#define HWD 256        // 16*16 pixels per frame
#define PP 16          // parts
#define CT 16          // channels per tile
#define PIT 260        // pitch: 16B-aligned rows, 2-way worst-case LDS
#define TILES 2        // tiles per block (block covers 32 channels)
#define SLICES 8       // channel slices per frame

#define CP_ASYNC16(dst, src) \
    asm volatile("cp.async.cg.shared.global [%0], [%1], 16;" :: "r"(dst), "l"(src) : "memory")
#define CP_COMMIT() asm volatile("cp.async.commit_group;" ::: "memory")
#define CP_WAIT(n)  asm volatile("cp.async.wait_group %0;" :: "n"(n) : "memory")

__global__ __launch_bounds__(256, 6)
void part_pool_kernel(const float* __restrict__ x,
                      const void* __restrict__ labels_raw,
                      float* __restrict__ out)
{
    extern __shared__ float tiles[];      // 2 * CT*PIT floats = 33,280 B
    __shared__ float pooled[CT * 17];
    __shared__ int   order[HWD];
    __shared__ int   cnt[PP], off[PP], fill[PP];

    const int bid = blockIdx.x;           // 0..7679
    const int f   = bid >> 3;             // frame
    const int q   = bid & 7;              // channel slice (32 channels)
    const int n = f / SS;
    const int s = f % SS;
    const int t = threadIdx.x;
    const int w = t >> 5;
    const int l = t & 31;

    // ---- fused label-dtype detection (frame 0 region: in-bounds both layouts).
    // int64 little-endian labels 0..15 -> odd 32-bit words all zero.
    if (t < PP) { cnt[t] = 0; fill[t] = 0; }
    const int oddw = ((const int*)labels_raw)[2 * t + 1];
    const int lab64 = !__syncthreads_or(oddw != 0);   // also orders cnt/fill init

    // ---- per-frame label bucketing ----
    int myl;
    if (lab64) myl = (int)((const long long*)labels_raw)[(size_t)f * HWD + t];
    else       myl = ((const int*)labels_raw)[(size_t)f * HWD + t];
    myl &= (PP - 1);
    atomicAdd(&cnt[myl], 1);
    __syncthreads();

    if (t == 0) {
        int acc = 0;
        #pragma unroll
        for (int p = 0; p < PP; p++) { off[p] = acc; acc += cnt[p]; }
    }
    __syncthreads();
    order[off[myl] + atomicAdd(&fill[myl], 1)] = t;
    // order[] consumers pass the tile-ready __syncthreads below first.

    // base of this block's channel range for frame (n,s)
    const float* xf = x + ((size_t)(n * CC + q * (TILES * CT)) * SS + s) * HWD;
    const unsigned stile = (unsigned)__cvta_generic_to_shared(tiles);

    // 16B cp.async: thread t loads channel t>>4, 4 groups of 4 pixels (coalesced)
    const int lcl = t >> 4;
    const int lg  = t & 15;
    #define LOAD_TILE(tt, buf) do {                                            \
        const float* _row = xf + (size_t)((tt) * CT + lcl) * (SS * HWD);       \
        unsigned _dst = stile + (unsigned)(((buf) * CT + lcl) * (PIT * 4));    \
        _Pragma("unroll")                                                      \
        for (int _k = 0; _k < 4; _k++) {                                       \
            int _g = lg + 16 * _k;                                             \
            CP_ASYNC16(_dst + _g * 16, _row + _g * 4);                         \
        }                                                                      \
        CP_COMMIT();                                                           \
    } while (0)

    // per-lane fixed roles: half-warp owns one part, lane&15 = channel in tile
    const int p  = (w << 1) | (l >> 4);   // part 0..15
    const int cl = l & 15;                // channel-in-tile
    const int cN = cnt[p];
    const int o  = off[p];
    const float rc = (cN > 0) ? (1.0f / (float)cN) : 0.0f;  // prologue-shadow FDIV

    LOAD_TILE(0, 0);

    #pragma unroll
    for (int tt = 0; tt < TILES; tt++) {
        const int buf = tt & 1;
        if (tt + 1 < TILES) { LOAD_TILE(tt + 1, buf ^ 1); CP_WAIT(1); }
        else                { CP_WAIT(0); }
        __syncthreads();                  // tile tt visible to all

        const float* tb = tiles + (buf * CT + cl) * PIT;

        float sum = 0.0f;
        float mx  = -3.0e38f;
        #pragma unroll 4
        for (int j = 0; j < cN; j++) {
            float v = tb[order[o + j]];   // order: broadcast LDS per half-warp
            sum += v;
            mx = fmaxf(mx, v);
        }
        float r = 0.0f;
        if (cN > 0)
            r = sum * rc + fmaxf(mx, -100.0f);  // mean + amax(incl -100 init)
        pooled[cl * 17 + p] = r;

        __syncthreads();                  // pooled ready AND buffer reads done

        // coalesced store: thread t -> (channel t>>4, part t&15)
        {
            int cc = t >> 4;
            int pp = t & 15;
            int c  = q * (TILES * CT) + tt * CT + cc;
            out[((size_t)(n * CC + c) * SS + s) * PP + pp] = pooled[cc * 17 + pp];
        }
        // next iter's LOAD overwrites buf^1: its compute finished before the
        // sync above -> safe.
    }
    #undef LOAD_TILE
}

extern "C" void kernel_launch(void* const* d_in, const int* in_sizes, int n_in,
                              void* d_out, int out_size)
{
    const float* x      = (const float*)d_in[0];
    const void*  labels = d_in[1];
    float*       out    = (float*)d_out;

    cudaFuncSetAttribute(part_pool_kernel,
                         cudaFuncAttributeMaxDynamicSharedMemorySize,
                         2 * CT * PIT * 4);

    part_pool_kernel<<<NN * SS * SLICES, 256, 2 * CT * PIT * 4>>>(x, labels, out);
}

// round 10
// speedup vs baseline: 1.3325x; 1.0603x over previous
#include <cuda_runtime.h>

#define NN 32
#define CC 256
#define SS 30
#define HWD 256        // 16*16 pixels per frame
#define PP 16          // parts
#define CT 16          // channels per tile
#define PIT 260        // pitch: 16B-aligned rows, 2-way worst-case LDS
#define TILES 4        // tiles per block (block covers 64 channels)
#define SLICES 4       // channel slices per frame

#define CP_ASYNC16(dst, src) \
    asm volatile("cp.async.cg.shared.global [%0], [%1], 16;" :: "r"(dst), "l"(src) : "memory")
#define CP_COMMIT() asm volatile("cp.async.commit_group;" ::: "memory")
#define CP_WAIT(n)  asm volatile("cp.async.wait_group %0;" :: "n"(n) : "memory")

__global__ __launch_bounds__(256, 6)
void part_pool_kernel(const float* __restrict__ x,
                      const void* __restrict__ labels_raw,
                      float* __restrict__ out)
{
    extern __shared__ float tiles[];      // 2 * CT*PIT floats = 33,280 B
    __shared__ float pooled[CT * 17];
    __shared__ int   order[HWD];
    __shared__ int   off[PP], fill[PP];

    const int bid = blockIdx.x;           // 0..3839
    const int f   = bid >> 2;             // frame
    const int q   = bid & 3;              // channel slice (64 channels)
    const int n = f / SS;
    const int s = f % SS;
    const int t = threadIdx.x;
    const int w = t >> 5;
    const int l = t & 31;

    // base of this block's channel range for frame (n,s)
    const float* xf = x + ((size_t)(n * CC + q * (TILES * CT)) * SS + s) * HWD;
    const unsigned stile = (unsigned)__cvta_generic_to_shared(tiles);

    // 16B cp.async: thread t loads channel t>>4, 4 groups of 4 pixels (coalesced)
    const int lcl = t >> 4;
    const int lg  = t & 15;
    #define LOAD_TILE(tt, buf) do {                                            \
        const float* _row = xf + (size_t)((tt) * CT + lcl) * (SS * HWD);       \
        unsigned _dst = stile + (unsigned)(((buf) * CT + lcl) * (PIT * 4));    \
        _Pragma("unroll")                                                      \
        for (int _k = 0; _k < 4; _k++) {                                       \
            int _g = lg + 16 * _k;                                             \
            CP_ASYNC16(_dst + _g * 16, _row + _g * 4);                         \
        }                                                                      \
        CP_COMMIT();                                                           \
    } while (0)

    // ---- issue both tile loads BEFORE the prologue: no label dependence,
    // overlaps all bucketing latency with the first 32 KB of DRAM traffic.
    LOAD_TILE(0, 0);
    LOAD_TILE(1, 1);

    // ---- fused label-dtype detection (frame-0 region, in-bounds both layouts):
    // int64 little-endian labels 0..15 -> odd 32-bit words all zero.
    if (t < PP) fill[t] = 0;
    const int oddw = ((const int*)labels_raw)[2 * t + 1];
    const int lab64 = !__syncthreads_or(oddw != 0);   // also orders fill init

    // ---- per-frame label bucketing (single atomic phase) ----
    int myl;
    if (lab64) myl = (int)((const long long*)labels_raw)[(size_t)f * HWD + t];
    else       myl = ((const int*)labels_raw)[(size_t)f * HWD + t];
    myl &= (PP - 1);
    const int pos = atomicAdd(&fill[myl], 1);
    __syncthreads();                      // fill[p] == cnt[p] final

    // per-lane fixed roles: half-warp owns one part, lane&15 = channel in tile
    const int p  = (w << 1) | (l >> 4);   // part 0..15
    const int cl = l & 15;                // channel-in-tile
    const int cN = fill[p];
    const float rc = (cN > 0) ? (1.0f / (float)cN) : 0.0f;

    if (t == 0) {
        int acc = 0;
        #pragma unroll
        for (int pp = 0; pp < PP; pp++) { off[pp] = acc; acc += fill[pp]; }
    }
    __syncthreads();                      // off[] ready
    order[off[myl] + pos] = t;
    const int o = off[p];
    // order[] visibility to other warps: covered by the tile-ready sync below.

    for (int tt = 0; tt < TILES; tt++) {
        const int buf = tt & 1;
        if (tt + 1 < TILES) CP_WAIT(1);   // tile tt landed (one newer in flight)
        else                CP_WAIT(0);
        __syncthreads();                  // tile tt visible to all

        const float* tb = tiles + (buf * CT + cl) * PIT;

        float sum = 0.0f;
        float mx  = -3.0e38f;
        #pragma unroll 4
        for (int j = 0; j < cN; j++) {
            float v = tb[order[o + j]];   // order: broadcast LDS per half-warp
            sum += v;
            mx = fmaxf(mx, v);
        }
        float r = 0.0f;
        if (cN > 0)
            r = sum * rc + fmaxf(mx, -100.0f);  // mean + amax(incl -100 init)
        pooled[cl * 17 + p] = r;

        __syncthreads();                  // pooled ready AND buffer tt reads done

        // coalesced store: thread t -> (channel t>>4, part t&15)
        {
            int cc = t >> 4;
            int pp = t & 15;
            int c  = q * (TILES * CT) + tt * CT + cc;
            out[((size_t)(n * CC + c) * SS + s) * PP + pp] = pooled[cc * 17 + pp];
        }

        // refill this buffer with tile tt+2 (all warps finished reading it at
        // the sync above)
        if (tt + 2 < TILES) LOAD_TILE(tt + 2, buf);
    }
    #undef LOAD_TILE
}

extern "C" void kernel_launch(void* const* d_in, const int* in_sizes, int n_in,
                              void* d_out, int out_size)
{
    const float* x      = (const float*)d_in[0];
    const void*  labels = d_in[1];
    float*       out    = (float*)d_out;

    cudaFuncSetAttribute(part_pool_kernel,
                         cudaFuncAttributeMaxDynamicSharedMemorySize,
                         2 * CT * PIT * 4);

    part_pool_kernel<<<NN * SS * SLICES, 256, 2 * CT * PIT * 4>>>(x, labels, out);
}

// round 11
// speedup vs baseline: 1.4162x; 1.0628x over previous
#include <cuda_runtime.h>

#define NN 32
#define CC 256
#define SS 30
#define HWD 256        // 16*16 pixels per frame
#define PP 16          // parts
#define CT 16          // channels per tile
#define PIT 260        // pitch: 16B-aligned rows, 2-way worst-case LDS
#define TILES 4        // tiles per block (block covers 64 channels)
#define SLICES 4       // channel slices per frame

#define CP_ASYNC16(dst, src) \
    asm volatile("cp.async.cg.shared.global [%0], [%1], 16;" :: "r"(dst), "l"(src) : "memory")
#define CP_COMMIT() asm volatile("cp.async.commit_group;" ::: "memory")
#define CP_WAIT(n)  asm volatile("cp.async.wait_group %0;" :: "n"(n) : "memory")

__global__ __launch_bounds__(256, 6)
void part_pool_kernel(const float* __restrict__ x,
                      const void* __restrict__ labels_raw,
                      float* __restrict__ out)
{
    extern __shared__ float tiles[];      // 2 * CT*PIT floats = 33,280 B
    __shared__ float pooled[CT * 17];
    __shared__ unsigned int pk4w[(HWD + PP * 4) / 4];  // byte pixel lists, 4-aligned starts
    __shared__ int off4[PP], fill[PP];

    unsigned char* pk4 = (unsigned char*)pk4w;

    const int bid = blockIdx.x;           // 0..3839
    const int f   = bid >> 2;             // frame
    const int q   = bid & 3;              // channel slice (64 channels)
    const int n = f / SS;
    const int s = f % SS;
    const int t = threadIdx.x;
    const int w = t >> 5;
    const int l = t & 31;

    // base of this block's channel range for frame (n,s)
    const float* xf = x + ((size_t)(n * CC + q * (TILES * CT)) * SS + s) * HWD;
    const unsigned stile = (unsigned)__cvta_generic_to_shared(tiles);

    // 16B cp.async: thread t loads channel t>>4, 4 groups of 4 pixels (coalesced)
    const int lcl = t >> 4;
    const int lg  = t & 15;
    #define LOAD_TILE(tt, buf) do {                                            \
        const float* _row = xf + (size_t)((tt) * CT + lcl) * (SS * HWD);       \
        unsigned _dst = stile + (unsigned)(((buf) * CT + lcl) * (PIT * 4));    \
        _Pragma("unroll")                                                      \
        for (int _k = 0; _k < 4; _k++) {                                       \
            int _g = lg + 16 * _k;                                             \
            CP_ASYNC16(_dst + _g * 16, _row + _g * 4);                         \
        }                                                                      \
        CP_COMMIT();                                                           \
    } while (0)

    // ---- issue both tile loads BEFORE the prologue (no label dependence):
    // overlaps all bucketing latency with the first 32 KB of DRAM traffic.
    LOAD_TILE(0, 0);
    LOAD_TILE(1, 1);

    // ---- fused label-dtype detection (frame-0 region, in-bounds both layouts):
    // int64 little-endian labels 0..15 -> odd 32-bit words all zero.
    if (t < PP) fill[t] = 0;
    const int oddw = ((const int*)labels_raw)[2 * t + 1];
    const int lab64 = !__syncthreads_or(oddw != 0);   // also orders fill init

    // ---- per-frame label bucketing (single atomic phase) ----
    int myl;
    if (lab64) myl = (int)((const long long*)labels_raw)[(size_t)f * HWD + t];
    else       myl = ((const int*)labels_raw)[(size_t)f * HWD + t];
    myl &= (PP - 1);
    const int pos = atomicAdd(&fill[myl], 1);
    __syncthreads();                      // fill[p] == cnt[p] final

    // per-lane fixed roles: half-warp owns one part, lane&15 = channel in tile
    const int p  = (w << 1) | (l >> 4);   // part 0..15
    const int cl = l & 15;                // channel-in-tile
    const int cN = fill[p];
    const float rc = (cN > 0) ? (1.0f / (float)cN) : 0.0f;

    if (t == 0) {
        int acc = 0;
        #pragma unroll
        for (int pp = 0; pp < PP; pp++) { off4[pp] = acc; acc += (fill[pp] + 3) & ~3; }
    }
    __syncthreads();                      // off4[] ready
    pk4[off4[myl] + pos] = (unsigned char)t;   // byte pixel list write
    // pk4 visibility to other warps: covered by the first tile-ready sync.

    const unsigned int* mylist = pk4w + (off4[p] >> 2);
    const int kW = cN >> 2;               // full 4-pixel words
    const int kR = cN & 3;                // tail pixels in final word

    for (int tt = 0; tt < TILES; tt++) {
        const int buf = tt & 1;
        if (tt + 1 < TILES) CP_WAIT(1);   // tile tt landed (one newer in flight)
        else                CP_WAIT(0);
        __syncthreads();                  // tile tt visible to all

        const float* tb = tiles + (buf * CT + cl) * PIT;

        float sum = 0.0f;
        float mx  = -3.0e38f;
        #pragma unroll 2
        for (int k = 0; k < kW; k++) {
            unsigned u = mylist[k];       // 1 broadcast LDS -> 4 pixel ids
            float a = tb[u & 255u];
            float b = tb[(u >> 8) & 255u];
            float c = tb[(u >> 16) & 255u];
            float d = tb[u >> 24];
            sum += (a + b) + (c + d);
            mx = fmaxf(fmaxf(fmaxf(a, b), fmaxf(c, d)), mx);
        }
        if (kR) {                         // tail: only written bytes extracted
            unsigned u = mylist[kW];
            #pragma unroll
            for (int j = 0; j < 3; j++) {
                if (j < kR) {
                    float v = tb[(u >> (8 * j)) & 255u];
                    sum += v;
                    mx = fmaxf(mx, v);
                }
            }
        }

        float r = 0.0f;
        if (cN > 0)
            r = sum * rc + fmaxf(mx, -100.0f);  // mean + amax(incl -100 init)
        pooled[cl * 17 + p] = r;

        __syncthreads();                  // pooled ready AND buffer tt reads done

        // coalesced store: thread t -> (channel t>>4, part t&15)
        {
            int cc = t >> 4;
            int pp = t & 15;
            int c  = q * (TILES * CT) + tt * CT + cc;
            out[((size_t)(n * CC + c) * SS + s) * PP + pp] = pooled[cc * 17 + pp];
        }

        // refill this buffer with tile tt+2 (all warps done reading it above)
        if (tt + 2 < TILES) LOAD_TILE(tt + 2, buf);
    }
    #undef LOAD_TILE
}

extern "C" void kernel_launch(void* const* d_in, const int* in_sizes, int n_in,
                              void* d_out, int out_size)
{
    const float* x      = (const float*)d_in[0];
    const void*  labels = d_in[1];
    float*       out    = (float*)d_out;

    cudaFuncSetAttribute(part_pool_kernel,
                         cudaFuncAttributeMaxDynamicSharedMemorySize,
                         2 * CT * PIT * 4);

    part_pool_kernel<<<NN * SS * SLICES, 256, 2 * CT * PIT * 4>>>(x, labels, out);
}